// round 4
// baseline (speedup 1.0000x reference)
#include <cuda_runtime.h>
#include <cstdint>

#define Mdim 8192   // batch
#define Ndim 8192   // hidden
#define Kdim 256    // d_in
#define SAEK 32
#define CCAP 4096   // candidate capacity per row
#define THRESH 1.0f

// Scratch (allocation-free rule: static __device__ globals)
__device__ float  g_xhi[(size_t)Mdim * Kdim];
__device__ float  g_xlo[(size_t)Mdim * Kdim];
__device__ float  g_whi[(size_t)Ndim * Kdim];
__device__ float  g_wlo[(size_t)Ndim * Kdim];
__device__ int    g_ccnt[Mdim];
__device__ float2 g_cand[(size_t)Mdim * CCAP];   // (val, col-as-bits) 256 MB
__device__ int    g_tk_idx[Mdim * SAEK];
__device__ float  g_tk_val[Mdim * SAEK];

// ---------------------------------------------------------------------------
// family-portable PTX helpers (sm_80 baseline — harness targets sm_103 plain)
// ---------------------------------------------------------------------------
__device__ __forceinline__ void cp_async16(uint32_t s, const void* g) {
    asm volatile("cp.async.cg.shared.global [%0], [%1], 16;" :: "r"(s), "l"(g));
}
#define CP_COMMIT() asm volatile("cp.async.commit_group;" ::: "memory")
#define CP_WAIT1()  asm volatile("cp.async.wait_group 1;" ::: "memory")
#define CP_WAIT0()  asm volatile("cp.async.wait_group 0;" ::: "memory")

__device__ __forceinline__ uint32_t smem_u32(const void* p) {
    uint32_t a;
    asm("{ .reg .u64 t; cvta.to.shared.u64 t, %1; cvt.u32.u64 %0, t; }" : "=r"(a) : "l"(p));
    return a;
}

__device__ __forceinline__ void mma_tf32(float* d, const uint32_t* a, const uint32_t* b) {
    asm volatile(
        "mma.sync.aligned.m16n8k8.row.col.f32.tf32.tf32.f32 "
        "{%0,%1,%2,%3}, {%4,%5,%6,%7}, {%8,%9}, {%0,%1,%2,%3};"
        : "+f"(d[0]), "+f"(d[1]), "+f"(d[2]), "+f"(d[3])
        : "r"(a[0]), "r"(a[1]), "r"(a[2]), "r"(a[3]), "r"(b[0]), "r"(b[1]));
}

// ---------------------------------------------------------------------------
// Kernel 0: split (x - b_dec) and W_enc into tf32-rounded hi/lo planes;
//           also zero the per-row candidate counters.
// ---------------------------------------------------------------------------
__global__ __launch_bounds__(256)
void prep_split(const float* __restrict__ x, const float* __restrict__ Wenc,
                const float* __restrict__ b_dec)
{
    const size_t XN = (size_t)Mdim * Kdim;
    size_t i = (size_t)blockIdx.x * 256 + threadIdx.x;
    if (i < Mdim) g_ccnt[i] = 0;

    float v;
    float *dhi, *dlo;
    if (i < XN) {
        v = x[i] - b_dec[i & (Kdim - 1)];
        dhi = g_xhi + i; dlo = g_xlo + i;
    } else {
        size_t j = i - XN;
        v = Wenc[j];
        dhi = g_whi + j; dlo = g_wlo + j;
    }
    uint32_t hb;
    asm("cvt.rna.tf32.f32 %0, %1;" : "=r"(hb) : "f"(v));
    float hi = __uint_as_float(hb);
    float lo = v - hi;
    uint32_t lb;
    asm("cvt.rna.tf32.f32 %0, %1;" : "=r"(lb) : "f"(lo));
    *dhi = hi;
    *dlo = __uint_as_float(lb);
}

// ---------------------------------------------------------------------------
// Kernel 1: 3xTF32 mma.sync encoder GEMM with candidate-compaction epilogue.
// Tile 128x128, BK=16, 2-stage cp.async, 8 warps (warp tile 64x32).
// Smem row stride = 20 floats (16 + 4 pad) -> conflict-free fragment loads.
// ---------------------------------------------------------------------------
#define BK 16
#define SPAD 20                 // floats per smem row
#define TILE_F (128 * SPAD)     // floats per tile (2560)
#define STAGE_F (4 * TILE_F)    // Ahi|Alo|Bhi|Blo
#define NCHUNK (Kdim / BK)      // 16

__global__ __launch_bounds__(256, 2)
void enc_gemm_mma(const float* __restrict__ b_enc)
{
    extern __shared__ float sm[];

    const int tid  = threadIdx.x;
    const int wid  = tid >> 5;
    const int lane = tid & 31;
    const int gid  = lane >> 2;     // 0..7
    const int tig  = lane & 3;      // 0..3
    const int wm   = wid & 1;       // 2 warps in M
    const int wn   = wid >> 1;      // 4 warps in N
    const int m0 = blockIdx.y * 128;
    const int n0 = blockIdx.x * 128;

    float acc[4][4][4];             // [mt][nt][frag]
#pragma unroll
    for (int a = 0; a < 4; a++)
#pragma unroll
        for (int b = 0; b < 4; b++)
#pragma unroll
            for (int c = 0; c < 4; c++) acc[a][b][c] = 0.f;

    // cp.async mapping: thread -> (row, 8-float half) per tile
    const int prow = tid >> 1;
    const int pc8  = (tid & 1) * 8;
    const uint32_t smb = smem_u32(sm);

    auto prefetch = [&](int c) {
        const int stage = c & 1;
        const int kofs = c * BK;
        const uint32_t sb = smb + (uint32_t)(stage * STAGE_F) * 4u;
        const uint32_t so = (uint32_t)(prow * SPAD + pc8) * 4u;
        const size_t ga = (size_t)(m0 + prow) * Kdim + kofs + pc8;
        const size_t gb = (size_t)(n0 + prow) * Kdim + kofs + pc8;
        cp_async16(sb + 0 * TILE_F * 4 + so,      g_xhi + ga);
        cp_async16(sb + 0 * TILE_F * 4 + so + 16, g_xhi + ga + 4);
        cp_async16(sb + 1 * TILE_F * 4 + so,      g_xlo + ga);
        cp_async16(sb + 1 * TILE_F * 4 + so + 16, g_xlo + ga + 4);
        cp_async16(sb + 2 * TILE_F * 4 + so,      g_whi + gb);
        cp_async16(sb + 2 * TILE_F * 4 + so + 16, g_whi + gb + 4);
        cp_async16(sb + 3 * TILE_F * 4 + so,      g_wlo + gb);
        cp_async16(sb + 3 * TILE_F * 4 + so + 16, g_wlo + gb + 4);
        CP_COMMIT();
    };

    prefetch(0);

    for (int c = 0; c < NCHUNK; c++) {
        if (c + 1 < NCHUNK) { prefetch(c + 1); CP_WAIT1(); }
        else                { CP_WAIT0(); }
        __syncthreads();

        const float* st = sm + (c & 1) * STAGE_F;
        const float* sAhi = st;
        const float* sAlo = st + TILE_F;
        const float* sBhi = st + 2 * TILE_F;
        const float* sBlo = st + 3 * TILE_F;

#pragma unroll
        for (int ks = 0; ks < 2; ks++) {
            const int kb = ks * 8;
            // B fragments for 4 n-tiles (hi & lo)
            uint32_t bh[4][2], bl[4][2];
#pragma unroll
            for (int nt = 0; nt < 4; nt++) {
                const int nrow = wn * 32 + nt * 8 + gid;
                bh[nt][0] = __float_as_uint(sBhi[nrow * SPAD + kb + tig]);
                bh[nt][1] = __float_as_uint(sBhi[nrow * SPAD + kb + tig + 4]);
                bl[nt][0] = __float_as_uint(sBlo[nrow * SPAD + kb + tig]);
                bl[nt][1] = __float_as_uint(sBlo[nrow * SPAD + kb + tig + 4]);
            }
#pragma unroll
            for (int mt = 0; mt < 4; mt++) {
                const int r0 = wm * 64 + mt * 16 + gid;
                uint32_t ah[4], al[4];
                ah[0] = __float_as_uint(sAhi[(r0)     * SPAD + kb + tig]);
                ah[1] = __float_as_uint(sAhi[(r0 + 8) * SPAD + kb + tig]);
                ah[2] = __float_as_uint(sAhi[(r0)     * SPAD + kb + tig + 4]);
                ah[3] = __float_as_uint(sAhi[(r0 + 8) * SPAD + kb + tig + 4]);
                al[0] = __float_as_uint(sAlo[(r0)     * SPAD + kb + tig]);
                al[1] = __float_as_uint(sAlo[(r0 + 8) * SPAD + kb + tig]);
                al[2] = __float_as_uint(sAlo[(r0)     * SPAD + kb + tig + 4]);
                al[3] = __float_as_uint(sAlo[(r0 + 8) * SPAD + kb + tig + 4]);
#pragma unroll
                for (int nt = 0; nt < 4; nt++) {
                    mma_tf32(acc[mt][nt], ah, bh[nt]);   // hi*hi
                    mma_tf32(acc[mt][nt], ah, bl[nt]);   // hi*lo
                    mma_tf32(acc[mt][nt], al, bh[nt]);   // lo*hi
                }
            }
        }
        __syncthreads();
    }

    // epilogue: + b_enc, relu, threshold-compact append
#pragma unroll
    for (int nt = 0; nt < 4; nt++) {
        const int gc0 = n0 + wn * 32 + nt * 8 + 2 * tig;
        const float be0 = __ldg(b_enc + gc0);
        const float be1 = __ldg(b_enc + gc0 + 1);
#pragma unroll
        for (int mt = 0; mt < 4; mt++) {
            const int gr0 = m0 + wm * 64 + mt * 16 + gid;
            float v00 = acc[mt][nt][0] + be0;
            float v01 = acc[mt][nt][1] + be1;
            float v10 = acc[mt][nt][2] + be0;
            float v11 = acc[mt][nt][3] + be1;
            if (v00 >= THRESH) {
                int p = atomicAdd(&g_ccnt[gr0], 1);
                if (p < CCAP) g_cand[(size_t)gr0 * CCAP + p] = make_float2(v00, __int_as_float(gc0));
            }
            if (v01 >= THRESH) {
                int p = atomicAdd(&g_ccnt[gr0], 1);
                if (p < CCAP) g_cand[(size_t)gr0 * CCAP + p] = make_float2(v01, __int_as_float(gc0 + 1));
            }
            if (v10 >= THRESH) {
                int p = atomicAdd(&g_ccnt[gr0 + 8], 1);
                if (p < CCAP) g_cand[(size_t)(gr0 + 8) * CCAP + p] = make_float2(v10, __int_as_float(gc0));
            }
            if (v11 >= THRESH) {
                int p = atomicAdd(&g_ccnt[gr0 + 8], 1);
                if (p < CCAP) g_cand[(size_t)(gr0 + 8) * CCAP + p] = make_float2(v11, __int_as_float(gc0 + 1));
            }
        }
    }
}

// ---------------------------------------------------------------------------
// Kernel 2: top-32 from candidate list (histogram select); dense fallback for
//           statistically-impossible rows (count < 32 or overflow).
// ---------------------------------------------------------------------------
#define NBINS 2048
#define BCAP 512

__global__ __launch_bounds__(256)
void topk_cand(const float* __restrict__ x, const float* __restrict__ Wenc,
               const float* __restrict__ b_enc, const float* __restrict__ b_dec)
{
    __shared__ __align__(16) char s_store[32768];   // union: float2[4096] | float[8192]
    float2* s_pair = (float2*)s_store;
    float*  s_row  = (float*)s_store;
    __shared__ unsigned s_hist[NBINS];
    __shared__ unsigned s_g[256];
    __shared__ int      s_bound[BCAP];
    __shared__ float    s_rv[256];
    __shared__ int      s_ri[256];
    __shared__ int      s_sel_idx[SAEK];
    __shared__ float    s_sel_val[SAEK];
    __shared__ int      s_nsel, s_nbound, s_bstar, s_chi;
    __shared__ float    s_xr[Kdim];

    const int row = blockIdx.x;
    const int tid = threadIdx.x;
    const int n = g_ccnt[row];

    if (n >= SAEK && n <= CCAP) {
        // ---- candidate path ----
        for (int i = tid; i < n; i += 256) s_pair[i] = g_cand[(size_t)row * CCAP + i];
        for (int i = tid; i < NBINS; i += 256) s_hist[i] = 0;
        __syncthreads();

        for (int i = tid; i < n; i += 256)
            atomicAdd(&s_hist[__float_as_uint(s_pair[i].x) >> 20], 1u);
        __syncthreads();

        unsigned gs = 0;
#pragma unroll
        for (int j = 0; j < 8; j++) gs += s_hist[tid * 8 + j];
        s_g[tid] = gs;
        __syncthreads();

        if (tid == 0) {
            unsigned run = 0; int fb = 0, fchi = 0;
            for (int g = 255; g >= 0; g--) {
                unsigned nr = run + s_g[g];
                if (nr >= SAEK) {
                    unsigned ca = run;
                    for (int b = g * 8 + 7; b >= g * 8; b--) {
                        unsigned h = s_hist[b];
                        if (ca + h >= SAEK) { fb = b; fchi = (int)ca; break; }
                        ca += h;
                    }
                    break;
                }
                run = nr;
            }
            s_bstar = fb; s_chi = fchi;
            s_nsel = 0; s_nbound = 0;
        }
        __syncthreads();
        const int bstar = s_bstar;
        const int chi = s_chi;

        for (int i = tid; i < n; i += 256) {
            int b = (int)(__float_as_uint(s_pair[i].x) >> 20);
            if (b > bstar) {
                int p = atomicAdd(&s_nsel, 1);
                s_sel_idx[p] = __float_as_int(s_pair[i].y);
                s_sel_val[p] = s_pair[i].x;
            } else if (b == bstar) {
                int p = atomicAdd(&s_nbound, 1);
                if (p < BCAP) s_bound[p] = i;
            }
        }
        __syncthreads();

        const int m = SAEK - chi;
        const bool ovf = (s_nbound > BCAP);
        const int nb = ovf ? 0 : s_nbound;

        for (int it = 0; it < m; it++) {
            float bv = -1.0f; int bi = 0x7FFFFFFF;
            if (!ovf) {
                for (int j = tid; j < nb; j += 256) {
                    float v = s_pair[s_bound[j]].x;
                    int ci = __float_as_int(s_pair[s_bound[j]].y);
                    if (v > bv || (v == bv && ci < bi)) { bv = v; bi = ci; }
                }
            } else {
                for (int i = tid; i < n; i += 256) {
                    float v = s_pair[i].x;
                    if ((int)(__float_as_uint(v) >> 20) == bstar) {
                        int ci = __float_as_int(s_pair[i].y);
                        if (v > bv || (v == bv && ci < bi)) { bv = v; bi = ci; }
                    }
                }
            }
            s_rv[tid] = bv; s_ri[tid] = bi;
            __syncthreads();
#pragma unroll
            for (int s = 128; s > 0; s >>= 1) {
                if (tid < s) {
                    float ov = s_rv[tid + s]; int oi = s_ri[tid + s];
                    if (ov > s_rv[tid] || (ov == s_rv[tid] && oi < s_ri[tid])) {
                        s_rv[tid] = ov; s_ri[tid] = oi;
                    }
                }
                __syncthreads();
            }
            if (tid == 0) {
                s_sel_idx[chi + it] = s_ri[0];
                s_sel_val[chi + it] = s_rv[0];
            }
            // mark the winner as taken
            if (!ovf) {
                for (int j = tid; j < nb; j += 256)
                    if (__float_as_int(s_pair[s_bound[j]].y) == s_ri[0] &&
                        s_pair[s_bound[j]].x == s_rv[0])
                        s_pair[s_bound[j]].x = -2.0f;
            } else {
                for (int i = tid; i < n; i += 256)
                    if (__float_as_int(s_pair[i].y) == s_ri[0] && s_pair[i].x == s_rv[0])
                        s_pair[i].x = -2.0f;
            }
            __syncthreads();
        }
    } else {
        // ---- dense fallback (never expected statistically) ----
        s_xr[tid] = x[(size_t)row * Kdim + tid] - b_dec[tid];
        __syncthreads();
        for (int col = tid; col < Ndim; col += 256) {
            float a = 0.f;
            const float* wr = Wenc + (size_t)col * Kdim;
            for (int d = 0; d < Kdim; d++) a = fmaf(s_xr[d], __ldg(wr + d), a);
            s_row[col] = fmaxf(a + __ldg(b_enc + col), 0.f);
        }
        __syncthreads();
        for (int it = 0; it < SAEK; it++) {
            float bv = -1.0f; int bi = 0x7FFFFFFF;
            for (int i = tid; i < Ndim; i += 256) {
                float v = s_row[i];
                if (v > bv || (v == bv && i < bi)) { bv = v; bi = i; }
            }
            s_rv[tid] = bv; s_ri[tid] = bi;
            __syncthreads();
#pragma unroll
            for (int s = 128; s > 0; s >>= 1) {
                if (tid < s) {
                    float ov = s_rv[tid + s]; int oi = s_ri[tid + s];
                    if (ov > s_rv[tid] || (ov == s_rv[tid] && oi < s_ri[tid])) {
                        s_rv[tid] = ov; s_ri[tid] = oi;
                    }
                }
                __syncthreads();
            }
            if (tid == 0) {
                s_sel_idx[it] = s_ri[0];
                s_sel_val[it] = fmaxf(s_rv[0], 0.f);
                s_row[s_ri[0]] = -2.0f;
            }
            __syncthreads();
        }
    }

    if (tid < SAEK) {
        g_tk_idx[row * SAEK + tid] = s_sel_idx[tid];
        g_tk_val[row * SAEK + tid] = s_sel_val[tid];
    }
}

// ---------------------------------------------------------------------------
// Kernel 3: sparse decode: out[b,:] = b_dec + sum_k val_k * W_dec[idx_k,:]
// ---------------------------------------------------------------------------
__global__ __launch_bounds__(256)
void decode_kernel(const float* __restrict__ Wdec, const float* __restrict__ b_dec,
                   float* __restrict__ out)
{
    const int row = blockIdx.x;
    const int d = threadIdx.x;
    __shared__ int   si[SAEK];
    __shared__ float sv[SAEK];
    if (d < SAEK) {
        si[d] = g_tk_idx[row * SAEK + d];
        sv[d] = g_tk_val[row * SAEK + d];
    }
    __syncthreads();

    float acc = b_dec[d];
#pragma unroll
    for (int j = 0; j < SAEK; j++)
        acc = fmaf(sv[j], __ldg(Wdec + (size_t)si[j] * Kdim + d), acc);
    out[(size_t)row * Kdim + d] = acc;
}

// ---------------------------------------------------------------------------
extern "C" void kernel_launch(void* const* d_in, const int* in_sizes, int n_in,
                              void* d_out, int out_size)
{
    const float* x     = (const float*)d_in[0];
    const float* W_enc = (const float*)d_in[1];
    const float* b_enc = (const float*)d_in[2];
    const float* W_dec = (const float*)d_in[3];
    const float* b_dec = (const float*)d_in[4];
    float* out = (float*)d_out;

    const int gemm_smem = 2 * STAGE_F * 4;   // 81920 B
    cudaFuncSetAttribute(enc_gemm_mma, cudaFuncAttributeMaxDynamicSharedMemorySize, gemm_smem);

    const int prep_blocks = (int)(((size_t)Mdim * Kdim + (size_t)Ndim * Kdim) / 256);
    prep_split<<<prep_blocks, 256>>>(x, W_enc, b_dec);

    dim3 g1(Ndim / 128, Mdim / 128);
    enc_gemm_mma<<<g1, 256, gemm_smem>>>(b_enc);

    topk_cand<<<Mdim, 256>>>(x, W_enc, b_enc, b_dec);
    decode_kernel<<<Mdim, 256>>>(W_dec, b_dec, out);
}

// round 5
// speedup vs baseline: 2.3049x; 2.3049x over previous
#include <cuda_runtime.h>
#include <cuda_bf16.h>
#include <cstdint>

#define Mdim 8192
#define Ndim 8192
#define Kdim 256
#define SAEK 32
#define CCAP 512
#define TCOEF 0.1375f   // 2.2 sigma / 16
#define ECOEF 0.0025f   // ~14 sigma screening-error bound / ||x||

// ---------------- device scratch (no allocs allowed) ----------------
__device__ uint32_t g_xb[(size_t)Mdim * Kdim / 2];   // bf16x2 packed (x - b_dec)
__device__ uint32_t g_wb[(size_t)Ndim * Kdim / 2];   // bf16x2 packed W_enc
__device__ float    g_rnorm[Mdim];
__device__ int      g_ccnt[Mdim];
__device__ int      g_cand_col[(size_t)Mdim * CCAP];
__device__ int      g_tk_idx[Mdim * SAEK];
__device__ float    g_tk_val[Mdim * SAEK];

// ---------------- portable PTX helpers (sm_80-level only) ----------------
__device__ __forceinline__ uint32_t smem_u32(const void* p) {
    uint32_t a;
    asm("{ .reg .u64 t; cvta.to.shared.u64 t, %1; cvt.u32.u64 %0, t; }" : "=r"(a) : "l"(p));
    return a;
}
__device__ __forceinline__ void cp_async16(uint32_t s, const void* g) {
    asm volatile("cp.async.cg.shared.global [%0], [%1], 16;" :: "r"(s), "l"(g));
}
#define CP_COMMIT() asm volatile("cp.async.commit_group;" ::: "memory")

#define LDSM_X4(r0,r1,r2,r3,addr) \
    asm volatile("ldmatrix.sync.aligned.m8n8.x4.shared.b16 {%0,%1,%2,%3}, [%4];" \
        : "=r"(r0),"=r"(r1),"=r"(r2),"=r"(r3) : "r"(addr))
#define LDSM_X2(r0,r1,addr) \
    asm volatile("ldmatrix.sync.aligned.m8n8.x2.shared.b16 {%0,%1}, [%2];" \
        : "=r"(r0),"=r"(r1) : "r"(addr))
#define MMA_BF16(d,a,b) \
    asm volatile("mma.sync.aligned.m16n8k16.row.col.f32.bf16.bf16.f32 " \
        "{%0,%1,%2,%3},{%4,%5,%6,%7},{%8,%9},{%0,%1,%2,%3};" \
        : "+f"((d)[0]),"+f"((d)[1]),"+f"((d)[2]),"+f"((d)[3]) \
        : "r"((a)[0]),"r"((a)[1]),"r"((a)[2]),"r"((a)[3]),"r"((b)[0]),"r"((b)[1]))

__device__ __forceinline__ uint32_t pack_bf16x2(float lo, float hi) {
    uint32_t r;
    asm("cvt.rn.bf16x2.f32 %0, %1, %2;" : "=r"(r) : "f"(hi), "f"(lo));
    return r;
}

// ---------------------------------------------------------------------------
// Kernel: per-row ||x - b_dec||  (one warp per row)
// ---------------------------------------------------------------------------
__global__ __launch_bounds__(256)
void norm_kernel(const float* __restrict__ x, const float* __restrict__ b_dec)
{
    const int wid = threadIdx.x >> 5, lane = threadIdx.x & 31;
    const int row = blockIdx.x * 8 + wid;
    const float* xr = x + (size_t)row * Kdim;
    float s = 0.f;
#pragma unroll
    for (int j = 0; j < 8; j++) {
        float e = xr[lane * 8 + j] - __ldg(b_dec + lane * 8 + j);
        s = fmaf(e, e, s);
    }
#pragma unroll
    for (int o = 16; o; o >>= 1) s += __shfl_down_sync(0xFFFFFFFFu, s, o);
    if (lane == 0) g_rnorm[row] = sqrtf(s);
}

// ---------------------------------------------------------------------------
// Kernel: pack (x - b_dec) and W_enc to bf16
// ---------------------------------------------------------------------------
__global__ __launch_bounds__(256)
void prep_pack(const float* __restrict__ x, const float* __restrict__ Wenc,
               const float* __restrict__ b_dec)
{
    const size_t XT = (size_t)Mdim * Kdim / 8;   // threads for x part
    size_t i = (size_t)blockIdx.x * 256 + threadIdx.x;
    float v[8];
    uint32_t* dst;
    if (i < XT) {
        const size_t base = i * 8;
        const int k = (int)(base & (Kdim - 1));
        float4 a = *(const float4*)(x + base);
        float4 b = *(const float4*)(x + base + 4);
        v[0] = a.x - __ldg(b_dec + k + 0); v[1] = a.y - __ldg(b_dec + k + 1);
        v[2] = a.z - __ldg(b_dec + k + 2); v[3] = a.w - __ldg(b_dec + k + 3);
        v[4] = b.x - __ldg(b_dec + k + 4); v[5] = b.y - __ldg(b_dec + k + 5);
        v[6] = b.z - __ldg(b_dec + k + 6); v[7] = b.w - __ldg(b_dec + k + 7);
        dst = g_xb + i * 4;
    } else {
        const size_t base = (i - XT) * 8;
        float4 a = *(const float4*)(Wenc + base);
        float4 b = *(const float4*)(Wenc + base + 4);
        v[0] = a.x; v[1] = a.y; v[2] = a.z; v[3] = a.w;
        v[4] = b.x; v[5] = b.y; v[6] = b.z; v[7] = b.w;
        dst = g_wb + (i - XT) * 4;
    }
    uint4 o;
    o.x = pack_bf16x2(v[0], v[1]);
    o.y = pack_bf16x2(v[2], v[3]);
    o.z = pack_bf16x2(v[4], v[5]);
    o.w = pack_bf16x2(v[6], v[7]);
    *(uint4*)dst = o;
}

// ---------------------------------------------------------------------------
// Kernel: bf16 screening GEMM (128x128 tile, BK=32 bf16, 3-stage cp.async).
// Epilogue: append cols with (screened + b_enc) >= TCOEF * rnorm[row].
// smem rows padded to 40 bf16 (80B) -> conflict-free ldmatrix.
// ---------------------------------------------------------------------------
#define STAGE_B 20480u     // 2 tensors x 128 rows x 80B
#define TILE_B  10240u

__global__ __launch_bounds__(256, 1)
void screen_gemm(const float* __restrict__ b_enc)
{
    extern __shared__ char smc[];
    const uint32_t smb = smem_u32(smc);
    const int tid = threadIdx.x, lane = tid & 31, wid = tid >> 5;
    const int wm = wid & 1, wn = wid >> 1;
    const int m0 = blockIdx.y * 128, n0 = blockIdx.x * 128;

    float acc[4][4][4];
#pragma unroll
    for (int a = 0; a < 4; a++)
#pragma unroll
        for (int b = 0; b < 4; b++)
#pragma unroll
            for (int c = 0; c < 4; c++) acc[a][b][c] = 0.f;

    const int prow = tid >> 1;
    const int pu   = (tid & 1) * 2;

    auto prefetch = [&](int c) {
        const uint32_t st = smb + (uint32_t)(c % 3) * STAGE_B;
        const uint32_t da = st + (uint32_t)prow * 80u + (uint32_t)pu * 16u;
        const char* ga = (const char*)g_xb + ((size_t)(m0 + prow) * Kdim + c * 32) * 2 + pu * 16;
        const char* gb = (const char*)g_wb + ((size_t)(n0 + prow) * Kdim + c * 32) * 2 + pu * 16;
        cp_async16(da,               ga);
        cp_async16(da + 16,          ga + 16);
        cp_async16(da + TILE_B,      gb);
        cp_async16(da + TILE_B + 16, gb + 16);
        CP_COMMIT();
    };

    prefetch(0); prefetch(1);

    for (int c = 0; c < 8; c++) {
        if (c < 7) asm volatile("cp.async.wait_group 1;" ::: "memory");
        else       asm volatile("cp.async.wait_group 0;" ::: "memory");
        __syncthreads();

        const uint32_t sA = smb + (uint32_t)(c % 3) * STAGE_B;
        const uint32_t sB = sA + TILE_B;
#pragma unroll
        for (int kh = 0; kh < 2; kh++) {
            uint32_t af[4][4], bf[4][2];
#pragma unroll
            for (int mt = 0; mt < 4; mt++) {
                const uint32_t ad = sA + (uint32_t)(wm * 64 + mt * 16 + (lane & 15)) * 80u
                                  + (uint32_t)(kh * 32 + (lane >> 4) * 16);
                LDSM_X4(af[mt][0], af[mt][1], af[mt][2], af[mt][3], ad);
            }
#pragma unroll
            for (int nt = 0; nt < 4; nt++) {
                const uint32_t bd = sB + (uint32_t)(wn * 32 + nt * 8 + (lane & 7)) * 80u
                                  + (uint32_t)(kh * 32 + ((lane >> 3) & 1) * 16);
                LDSM_X2(bf[nt][0], bf[nt][1], bd);
            }
#pragma unroll
            for (int mt = 0; mt < 4; mt++)
#pragma unroll
                for (int nt = 0; nt < 4; nt++)
                    MMA_BF16(acc[mt][nt], af[mt], bf[nt]);
        }
        __syncthreads();
        if (c + 2 < 8) prefetch(c + 2);
    }

    // epilogue: threshold append
#pragma unroll
    for (int mt = 0; mt < 4; mt++) {
        const int r0 = m0 + wm * 64 + mt * 16 + (lane >> 2);
        const int r1 = r0 + 8;
        const float T0 = TCOEF * __ldg(g_rnorm + r0);
        const float T1 = TCOEF * __ldg(g_rnorm + r1);
#pragma unroll
        for (int nt = 0; nt < 4; nt++) {
            const int c0 = n0 + wn * 32 + nt * 8 + 2 * (lane & 3);
            const float be0 = __ldg(b_enc + c0);
            const float be1 = __ldg(b_enc + c0 + 1);
            float v0 = acc[mt][nt][0] + be0;
            float v1 = acc[mt][nt][1] + be1;
            float v2 = acc[mt][nt][2] + be0;
            float v3 = acc[mt][nt][3] + be1;
            if (v0 >= T0) { int p = atomicAdd(&g_ccnt[r0], 1); if (p < CCAP) g_cand_col[(size_t)r0 * CCAP + p] = c0; }
            if (v1 >= T0) { int p = atomicAdd(&g_ccnt[r0], 1); if (p < CCAP) g_cand_col[(size_t)r0 * CCAP + p] = c0 + 1; }
            if (v2 >= T1) { int p = atomicAdd(&g_ccnt[r1], 1); if (p < CCAP) g_cand_col[(size_t)r1 * CCAP + p] = c0; }
            if (v3 >= T1) { int p = atomicAdd(&g_ccnt[r1], 1); if (p < CCAP) g_cand_col[(size_t)r1 * CCAP + p] = c0 + 1; }
        }
    }
}

// ---------------------------------------------------------------------------
// Kernel: exact fp32 rescore of candidates + exact top-32 (+ dense fallback)
// ---------------------------------------------------------------------------
__global__ __launch_bounds__(256)
void rescore_topk(const float* __restrict__ x, const float* __restrict__ Wenc,
                  const float* __restrict__ b_enc, const float* __restrict__ b_dec)
{
    __shared__ float s_x[Kdim];
    __shared__ int   s_col[CCAP];
    __shared__ float s_val[CCAP];
    __shared__ float s_rv[8];
    __shared__ int   s_ri[8];
    __shared__ int   s_sel_i[SAEK];
    __shared__ float s_sel_v[SAEK];
    __shared__ float s_row[Ndim];       // dense fallback only (32 KB)
    __shared__ int   s_fb;

    const int row = blockIdx.x;
    const int tid = threadIdx.x;
    const int wid = tid >> 5, lane = tid & 31;

    s_x[tid] = x[(size_t)row * Kdim + tid] - __ldg(b_dec + tid);
    if (tid == 0) s_fb = 0;
    __syncthreads();

    const int n = g_ccnt[row];
    const float rn = g_rnorm[row];
    bool fb = (n < SAEK) || (n > CCAP);

    if (!fb) {
        for (int i = tid; i < n; i += 256) s_col[i] = g_cand_col[(size_t)row * CCAP + i];
        __syncthreads();

        // exact fp32 dot per candidate (one warp per candidate, strided)
        for (int c = wid; c < n; c += 8) {
            const float* wr = Wenc + (size_t)s_col[c] * Kdim + lane * 8;
            float4 w0 = *(const float4*)(wr);
            float4 w1 = *(const float4*)(wr + 4);
            const float* xr = s_x + lane * 8;
            float s = xr[0] * w0.x;
            s = fmaf(xr[1], w0.y, s); s = fmaf(xr[2], w0.z, s); s = fmaf(xr[3], w0.w, s);
            s = fmaf(xr[4], w1.x, s); s = fmaf(xr[5], w1.y, s); s = fmaf(xr[6], w1.z, s);
            s = fmaf(xr[7], w1.w, s);
#pragma unroll
            for (int o = 16; o; o >>= 1) s += __shfl_down_sync(0xFFFFFFFFu, s, o);
            if (lane == 0) s_val[c] = s + __ldg(b_enc + s_col[c]);
        }
        __syncthreads();

        // exact top-32 with tie -> lowest col
        for (int it = 0; it < SAEK; it++) {
            float bv = -1e30f; int bi = 0x7FFFFFFF;
            for (int i = tid; i < n; i += 256) {
                float v = s_val[i]; int cc = s_col[i];
                if (v > bv || (v == bv && cc < bi)) { bv = v; bi = cc; }
            }
#pragma unroll
            for (int o = 16; o; o >>= 1) {
                float ov = __shfl_down_sync(0xFFFFFFFFu, bv, o);
                int   oi = __shfl_down_sync(0xFFFFFFFFu, bi, o);
                if (ov > bv || (ov == bv && oi < bi)) { bv = ov; bi = oi; }
            }
            if (lane == 0) { s_rv[wid] = bv; s_ri[wid] = bi; }
            __syncthreads();
            if (tid == 0) {
                float wv = s_rv[0]; int wi = s_ri[0];
#pragma unroll
                for (int j = 1; j < 8; j++) {
                    if (s_rv[j] > wv || (s_rv[j] == wv && s_ri[j] < wi)) { wv = s_rv[j]; wi = s_ri[j]; }
                }
                s_sel_v[it] = wv; s_sel_i[it] = wi;
                s_rv[0] = wv; s_ri[0] = wi;
            }
            __syncthreads();
            const int win = s_ri[0];
            for (int i = tid; i < n; i += 256)
                if (s_col[i] == win) s_val[i] = -1e30f;
            __syncthreads();
        }

        // validity: exact 32nd must clear threshold + screening error bound
        if (tid == 0 && s_sel_v[SAEK - 1] < TCOEF * rn + ECOEF * rn + 1e-6f) s_fb = 1;
        __syncthreads();
        fb = (s_fb != 0);
    }

    if (fb) {
        // dense exact fallback (statistically never taken)
        for (int col = tid; col < Ndim; col += 256) {
            const float* wr = Wenc + (size_t)col * Kdim;
            float a = 0.f;
            for (int d = 0; d < Kdim; d += 4) {
                float4 w = *(const float4*)(wr + d);
                a = fmaf(s_x[d], w.x, a);   a = fmaf(s_x[d + 1], w.y, a);
                a = fmaf(s_x[d + 2], w.z, a); a = fmaf(s_x[d + 3], w.w, a);
            }
            s_row[col] = fmaxf(a + __ldg(b_enc + col), 0.f);
        }
        __syncthreads();
        for (int it = 0; it < SAEK; it++) {
            float bv = -1e30f; int bi = 0x7FFFFFFF;
            for (int i = tid; i < Ndim; i += 256) {
                float v = s_row[i];
                if (v > bv || (v == bv && i < bi)) { bv = v; bi = i; }
            }
#pragma unroll
            for (int o = 16; o; o >>= 1) {
                float ov = __shfl_down_sync(0xFFFFFFFFu, bv, o);
                int   oi = __shfl_down_sync(0xFFFFFFFFu, bi, o);
                if (ov > bv || (ov == bv && oi < bi)) { bv = ov; bi = oi; }
            }
            if (lane == 0) { s_rv[wid] = bv; s_ri[wid] = bi; }
            __syncthreads();
            if (tid == 0) {
                float wv = s_rv[0]; int wi = s_ri[0];
#pragma unroll
                for (int j = 1; j < 8; j++) {
                    if (s_rv[j] > wv || (s_rv[j] == wv && s_ri[j] < wi)) { wv = s_rv[j]; wi = s_ri[j]; }
                }
                s_sel_v[it] = wv; s_sel_i[it] = wi;
                s_row[wi] = -1e30f;
            }
            __syncthreads();
        }
    }

    if (tid < SAEK) {
        g_tk_idx[row * SAEK + tid] = s_sel_i[tid];
        g_tk_val[row * SAEK + tid] = s_sel_v[tid];
    }
}

// ---------------------------------------------------------------------------
// Kernel: sparse decode
// ---------------------------------------------------------------------------
__global__ __launch_bounds__(256)
void decode_kernel(const float* __restrict__ Wdec, const float* __restrict__ b_dec,
                   float* __restrict__ out)
{
    const int row = blockIdx.x;
    const int d = threadIdx.x;
    __shared__ int   si[SAEK];
    __shared__ float sv[SAEK];
    if (d < SAEK) {
        si[d] = g_tk_idx[row * SAEK + d];
        sv[d] = g_tk_val[row * SAEK + d];
    }
    __syncthreads();

    float acc = __ldg(b_dec + d);
#pragma unroll
    for (int j = 0; j < SAEK; j++)
        acc = fmaf(sv[j], __ldg(Wdec + (size_t)si[j] * Kdim + d), acc);
    out[(size_t)row * Kdim + d] = acc;
}

// ---------------------------------------------------------------------------
extern "C" void kernel_launch(void* const* d_in, const int* in_sizes, int n_in,
                              void* d_out, int out_size)
{
    const float* x     = (const float*)d_in[0];
    const float* W_enc = (const float*)d_in[1];
    const float* b_enc = (const float*)d_in[2];
    const float* W_dec = (const float*)d_in[3];
    const float* b_dec = (const float*)d_in[4];
    float* out = (float*)d_out;

    static void* ccnt_ptr = nullptr;
    if (!ccnt_ptr) cudaGetSymbolAddress(&ccnt_ptr, g_ccnt);
    static bool attr = false;
    if (!attr) {
        cudaFuncSetAttribute(screen_gemm, cudaFuncAttributeMaxDynamicSharedMemorySize,
                             3 * STAGE_B);
        attr = true;
    }

    cudaMemsetAsync(ccnt_ptr, 0, Mdim * sizeof(int));
    norm_kernel<<<Mdim / 8, 256>>>(x, b_dec);
    const int prep_blocks = (int)(((size_t)Mdim * Kdim + (size_t)Ndim * Kdim) / 8 / 256);
    prep_pack<<<prep_blocks, 256>>>(x, W_enc, b_dec);

    dim3 g1(Ndim / 128, Mdim / 128);
    screen_gemm<<<g1, 256, 3 * STAGE_B>>>(b_enc);

    rescore_topk<<<Mdim, 256>>>(x, W_enc, b_enc, b_dec);
    decode_kernel<<<Mdim, 256>>>(W_dec, b_dec, out);
}

// round 6
// speedup vs baseline: 3.4906x; 1.5144x over previous
#include <cuda_runtime.h>
#include <cstdint>

#define Mdim 8192
#define Ndim 8192
#define Kdim 256
#define SAEK 32
#define CCAP 512
#define TCOEF 0.1375f    // 2.2 sigma / 16
#define ECOEF 0.0100f    // int8 screening-error bound (abs / ||x||), ~12 sigma

// ---------------- device scratch ----------------
__device__ uint32_t g_x8[(size_t)Mdim * Kdim / 4];   // int8 packed (x - b_dec)
__device__ uint32_t g_w8[(size_t)Ndim * Kdim / 4];   // int8 packed W_enc
__device__ float    g_rnorm[Mdim];
__device__ float    g_sx[Mdim],  g_isx[Mdim];
__device__ float    g_sw[Ndim],  g_isw[Ndim];
__device__ int      g_ccnt[Mdim];
__device__ int      g_cand_col[(size_t)Mdim * CCAP];

// ---------------- portable PTX helpers ----------------
__device__ __forceinline__ uint32_t smem_u32(const void* p) {
    uint32_t a;
    asm("{ .reg .u64 t; cvta.to.shared.u64 t, %1; cvt.u32.u64 %0, t; }" : "=r"(a) : "l"(p));
    return a;
}
__device__ __forceinline__ void cp_async16(uint32_t s, const void* g) {
    asm volatile("cp.async.cg.shared.global [%0], [%1], 16;" :: "r"(s), "l"(g));
}
#define CP_COMMIT() asm volatile("cp.async.commit_group;" ::: "memory")

#define LDSM_X4(r0,r1,r2,r3,addr) \
    asm volatile("ldmatrix.sync.aligned.m8n8.x4.shared.b16 {%0,%1,%2,%3}, [%4];" \
        : "=r"(r0),"=r"(r1),"=r"(r2),"=r"(r3) : "r"(addr))
#define LDSM_X2(r0,r1,addr) \
    asm volatile("ldmatrix.sync.aligned.m8n8.x2.shared.b16 {%0,%1}, [%2];" \
        : "=r"(r0),"=r"(r1) : "r"(addr))
#define MMA_S8(d,a,b) \
    asm volatile("mma.sync.aligned.m16n8k32.row.col.s32.s8.s8.s32 " \
        "{%0,%1,%2,%3},{%4,%5,%6,%7},{%8,%9},{%0,%1,%2,%3};" \
        : "+r"((d)[0]),"+r"((d)[1]),"+r"((d)[2]),"+r"((d)[3]) \
        : "r"((a)[0]),"r"((a)[1]),"r"((a)[2]),"r"((a)[3]),"r"((b)[0]),"r"((b)[1]))

// ---------------------------------------------------------------------------
// Kernel: per-row stats. rows [0,Mdim): x rows -> norm + maxabs(x - b_dec).
//         rows [Mdim, Mdim+Ndim): W rows -> maxabs.
// One warp per row.
// ---------------------------------------------------------------------------
__global__ __launch_bounds__(256)
void stats_kernel(const float* __restrict__ x, const float* __restrict__ Wenc,
                  const float* __restrict__ b_dec)
{
    const int wid = threadIdx.x >> 5, lane = threadIdx.x & 31;
    const int row = blockIdx.x * 8 + wid;
    if (row < Mdim) {
        const float* xr = x + (size_t)row * Kdim + lane * 8;
        float s = 0.f, mx = 0.f;
#pragma unroll
        for (int j = 0; j < 8; j++) {
            float e = xr[j] - __ldg(b_dec + lane * 8 + j);
            s = fmaf(e, e, s);
            mx = fmaxf(mx, fabsf(e));
        }
#pragma unroll
        for (int o = 16; o; o >>= 1) {
            s  += __shfl_down_sync(0xFFFFFFFFu, s, o);
            mx = fmaxf(mx, __shfl_down_sync(0xFFFFFFFFu, mx, o));
        }
        if (lane == 0) {
            g_rnorm[row] = sqrtf(s);
            g_sx[row]  = mx * (1.f / 127.f);
            g_isx[row] = (mx > 0.f) ? (127.f / mx) : 0.f;
        }
    } else {
        const int r = row - Mdim;
        const float* wr = Wenc + (size_t)r * Kdim + lane * 8;
        float mx = 0.f;
#pragma unroll
        for (int j = 0; j < 8; j++) mx = fmaxf(mx, fabsf(wr[j]));
#pragma unroll
        for (int o = 16; o; o >>= 1) mx = fmaxf(mx, __shfl_down_sync(0xFFFFFFFFu, mx, o));
        if (lane == 0) {
            g_sw[r]  = mx * (1.f / 127.f);
            g_isw[r] = (mx > 0.f) ? (127.f / mx) : 0.f;
        }
    }
}

// ---------------------------------------------------------------------------
// Kernel: quantize (x - b_dec) and W_enc to int8 (16 elements / thread)
// ---------------------------------------------------------------------------
__device__ __forceinline__ uint32_t q4(const float* v, float inv) {
    int q0 = max(-127, min(127, __float2int_rn(v[0] * inv)));
    int q1 = max(-127, min(127, __float2int_rn(v[1] * inv)));
    int q2 = max(-127, min(127, __float2int_rn(v[2] * inv)));
    int q3 = max(-127, min(127, __float2int_rn(v[3] * inv)));
    return (uint32_t)(q0 & 255) | ((uint32_t)(q1 & 255) << 8) |
           ((uint32_t)(q2 & 255) << 16) | ((uint32_t)(q3 & 255) << 24);
}

__global__ __launch_bounds__(256)
void prep_pack_s8(const float* __restrict__ x, const float* __restrict__ Wenc,
                  const float* __restrict__ b_dec)
{
    const size_t XT = (size_t)Mdim * Kdim / 16;
    size_t i = (size_t)blockIdx.x * 256 + threadIdx.x;
    float v[16];
    float inv;
    uint32_t* dst;
    if (i < XT) {
        const size_t base = i * 16;
        const int row = (int)(base >> 8);
        const int k = (int)(base & (Kdim - 1));
        inv = __ldg(g_isx + row);
#pragma unroll
        for (int j = 0; j < 16; j += 4) {
            float4 a = *(const float4*)(x + base + j);
            v[j]   = a.x - __ldg(b_dec + k + j);
            v[j+1] = a.y - __ldg(b_dec + k + j + 1);
            v[j+2] = a.z - __ldg(b_dec + k + j + 2);
            v[j+3] = a.w - __ldg(b_dec + k + j + 3);
        }
        dst = g_x8 + i * 4;
    } else {
        const size_t base = (i - XT) * 16;
        const int row = (int)(base >> 8);
        inv = __ldg(g_isw + row);
#pragma unroll
        for (int j = 0; j < 16; j += 4) {
            float4 a = *(const float4*)(Wenc + base + j);
            v[j] = a.x; v[j+1] = a.y; v[j+2] = a.z; v[j+3] = a.w;
        }
        dst = g_w8 + (i - XT) * 4;
    }
    uint4 o;
    o.x = q4(v + 0,  inv);
    o.y = q4(v + 4,  inv);
    o.z = q4(v + 8,  inv);
    o.w = q4(v + 12, inv);
    *(uint4*)dst = o;
}

// ---------------------------------------------------------------------------
// Kernel: int8 screening GEMM. 128x128 tile, K-chunk = 32 int8 (one mma K),
// 3-stage cp.async, 8 warps (warp tile 64x32), smem rows 32B + 16B pad.
// Epilogue: append cols with dequant(val) + b_enc >= TCOEF * rnorm[row].
// ---------------------------------------------------------------------------
#define SROW 48u
#define TILE8 (128u * SROW)      // 6144 B
#define STAGE8 (2u * TILE8)      // 12288 B

__global__ __launch_bounds__(256, 2)
void screen_gemm_s8(const float* __restrict__ b_enc)
{
    extern __shared__ char smc[];
    const uint32_t smb = smem_u32(smc);
    const int tid = threadIdx.x, lane = tid & 31, wid = tid >> 5;
    const int wm = wid & 1, wn = wid >> 1;
    const int m0 = blockIdx.y * 128, n0 = blockIdx.x * 128;

    int acc[4][4][4];
#pragma unroll
    for (int a = 0; a < 4; a++)
#pragma unroll
        for (int b = 0; b < 4; b++)
#pragma unroll
            for (int c = 0; c < 4; c++) acc[a][b][c] = 0;

    const int prow = tid >> 1;
    const int half = tid & 1;

    auto prefetch = [&](int c) {
        const uint32_t st = smb + (uint32_t)(c % 3) * STAGE8;
        const uint32_t da = st + (uint32_t)prow * SROW + (uint32_t)half * 16u;
        const char* ga = (const char*)g_x8 + (size_t)(m0 + prow) * Kdim + c * 32 + half * 16;
        const char* gb = (const char*)g_w8 + (size_t)(n0 + prow) * Kdim + c * 32 + half * 16;
        cp_async16(da,         ga);
        cp_async16(da + TILE8, gb);
        CP_COMMIT();
    };

    prefetch(0); prefetch(1);

    for (int c = 0; c < 8; c++) {
        if (c < 7) asm volatile("cp.async.wait_group 1;" ::: "memory");
        else       asm volatile("cp.async.wait_group 0;" ::: "memory");
        __syncthreads();

        const uint32_t sA = smb + (uint32_t)(c % 3) * STAGE8;
        const uint32_t sB = sA + TILE8;

        uint32_t af[4][4], bf[4][2];
#pragma unroll
        for (int mt = 0; mt < 4; mt++) {
            const uint32_t ad = sA + (uint32_t)(wm * 64 + mt * 16 + (lane & 15)) * SROW
                              + (uint32_t)((lane >> 4) * 16);
            LDSM_X4(af[mt][0], af[mt][1], af[mt][2], af[mt][3], ad);
        }
#pragma unroll
        for (int nt = 0; nt < 4; nt++) {
            const uint32_t bd = sB + (uint32_t)(wn * 32 + nt * 8 + (lane & 7)) * SROW
                              + (uint32_t)(((lane >> 3) & 1) * 16);
            LDSM_X2(bf[nt][0], bf[nt][1], bd);
        }
#pragma unroll
        for (int mt = 0; mt < 4; mt++)
#pragma unroll
            for (int nt = 0; nt < 4; nt++)
                MMA_S8(acc[mt][nt], af[mt], bf[nt]);

        __syncthreads();
        if (c + 2 < 8) prefetch(c + 2);
    }

    // epilogue: dequant + threshold append
#pragma unroll
    for (int mt = 0; mt < 4; mt++) {
        const int r0 = m0 + wm * 64 + mt * 16 + (lane >> 2);
        const int r1 = r0 + 8;
        const float sx0 = __ldg(g_sx + r0), sx1 = __ldg(g_sx + r1);
        const float T0 = TCOEF * __ldg(g_rnorm + r0);
        const float T1 = TCOEF * __ldg(g_rnorm + r1);
#pragma unroll
        for (int nt = 0; nt < 4; nt++) {
            const int c0 = n0 + wn * 32 + nt * 8 + 2 * (lane & 3);
            const float sw0 = __ldg(g_sw + c0), sw1 = __ldg(g_sw + c0 + 1);
            const float be0 = __ldg(b_enc + c0), be1 = __ldg(b_enc + c0 + 1);
            float v0 = (float)acc[mt][nt][0] * (sx0 * sw0) + be0;
            float v1 = (float)acc[mt][nt][1] * (sx0 * sw1) + be1;
            float v2 = (float)acc[mt][nt][2] * (sx1 * sw0) + be0;
            float v3 = (float)acc[mt][nt][3] * (sx1 * sw1) + be1;
            if (v0 >= T0) { int p = atomicAdd(&g_ccnt[r0], 1); if (p < CCAP) g_cand_col[(size_t)r0 * CCAP + p] = c0; }
            if (v1 >= T0) { int p = atomicAdd(&g_ccnt[r0], 1); if (p < CCAP) g_cand_col[(size_t)r0 * CCAP + p] = c0 + 1; }
            if (v2 >= T1) { int p = atomicAdd(&g_ccnt[r1], 1); if (p < CCAP) g_cand_col[(size_t)r1 * CCAP + p] = c0; }
            if (v3 >= T1) { int p = atomicAdd(&g_ccnt[r1], 1); if (p < CCAP) g_cand_col[(size_t)r1 * CCAP + p] = c0 + 1; }
        }
    }
}

// ---------------------------------------------------------------------------
// Kernel: exact fp32 rescore + one-pass rank top-32 + fused decode.
// ---------------------------------------------------------------------------
__global__ __launch_bounds__(256)
void rescore_decode(const float* __restrict__ x, const float* __restrict__ Wenc,
                    const float* __restrict__ b_enc, const float* __restrict__ Wdec,
                    const float* __restrict__ b_dec, float* __restrict__ out)
{
    __shared__ float s_x[Kdim];
    __shared__ int   s_col[CCAP];
    __shared__ float s_val[CCAP];
    __shared__ float s_sel_v[SAEK];
    __shared__ int   s_sel_i[SAEK];
    __shared__ float s_rv[8];
    __shared__ int   s_ri[8];
    __shared__ float s_row[Ndim];     // dense fallback only (32 KB)
    __shared__ int   s_fb;

    const int row = blockIdx.x;
    const int tid = threadIdx.x;
    const int wid = tid >> 5, lane = tid & 31;

    s_x[tid] = x[(size_t)row * Kdim + tid] - __ldg(b_dec + tid);
    if (tid == 0) s_fb = 0;
    __syncthreads();

    const int n = g_ccnt[row];
    const float rn = g_rnorm[row];
    bool fb = (n < SAEK) || (n > CCAP);

    if (!fb) {
        for (int i = tid; i < n; i += 256) s_col[i] = g_cand_col[(size_t)row * CCAP + i];
        __syncthreads();

        // exact fp32 dot per candidate (warp per candidate)
        for (int c = wid; c < n; c += 8) {
            const float* wr = Wenc + (size_t)s_col[c] * Kdim + lane * 8;
            float4 w0 = *(const float4*)(wr);
            float4 w1 = *(const float4*)(wr + 4);
            const float* xr = s_x + lane * 8;
            float s = xr[0] * w0.x;
            s = fmaf(xr[1], w0.y, s); s = fmaf(xr[2], w0.z, s); s = fmaf(xr[3], w0.w, s);
            s = fmaf(xr[4], w1.x, s); s = fmaf(xr[5], w1.y, s); s = fmaf(xr[6], w1.z, s);
            s = fmaf(xr[7], w1.w, s);
#pragma unroll
            for (int o = 16; o; o >>= 1) s += __shfl_down_sync(0xFFFFFFFFu, s, o);
            if (lane == 0) s_val[c] = s + __ldg(b_enc + s_col[c]);
        }
        __syncthreads();

        // one-pass rank selection (keys unique: (val desc, col asc))
        for (int i = tid; i < n; i += 256) {
            const float vi = s_val[i];
            const int   ci = s_col[i];
            int r = 0;
            for (int j = 0; j < n; j++) {
                const float vj = s_val[j];
                r += (vj > vi) || (vj == vi && s_col[j] < ci);
            }
            if (r < SAEK) { s_sel_v[r] = vi; s_sel_i[r] = ci; }
        }
        __syncthreads();

        // validity gate: exact 32nd must clear threshold + screening error bound
        if (tid == 0 && s_sel_v[SAEK - 1] < (TCOEF + ECOEF) * rn + 1e-6f) s_fb = 1;
        __syncthreads();
        fb = (s_fb != 0);
    }

    if (fb) {
        // dense exact fallback (statistically near-never)
        for (int col = tid; col < Ndim; col += 256) {
            const float* wr = Wenc + (size_t)col * Kdim;
            float a = 0.f;
            for (int d = 0; d < Kdim; d += 4) {
                float4 w = *(const float4*)(wr + d);
                a = fmaf(s_x[d], w.x, a);     a = fmaf(s_x[d + 1], w.y, a);
                a = fmaf(s_x[d + 2], w.z, a); a = fmaf(s_x[d + 3], w.w, a);
            }
            s_row[col] = fmaxf(a + __ldg(b_enc + col), 0.f);
        }
        __syncthreads();
        for (int it = 0; it < SAEK; it++) {
            float bv = -1e30f; int bi = 0x7FFFFFFF;
            for (int i = tid; i < Ndim; i += 256) {
                float v = s_row[i];
                if (v > bv || (v == bv && i < bi)) { bv = v; bi = i; }
            }
#pragma unroll
            for (int o = 16; o; o >>= 1) {
                float ov = __shfl_down_sync(0xFFFFFFFFu, bv, o);
                int   oi = __shfl_down_sync(0xFFFFFFFFu, bi, o);
                if (ov > bv || (ov == bv && oi < bi)) { bv = ov; bi = oi; }
            }
            if (lane == 0) { s_rv[wid] = bv; s_ri[wid] = bi; }
            __syncthreads();
            if (tid == 0) {
                float wv = s_rv[0]; int wi = s_ri[0];
#pragma unroll
                for (int j = 1; j < 8; j++)
                    if (s_rv[j] > wv || (s_rv[j] == wv && s_ri[j] < wi)) { wv = s_rv[j]; wi = s_ri[j]; }
                s_sel_v[it] = wv; s_sel_i[it] = wi;
                s_row[wi] = -1e30f;
            }
            __syncthreads();
        }
    }

    // fused decode: out[row, d] = b_dec[d] + sum_j sel_v[j] * W_dec[sel_i[j], d]
    const int d = tid;
    float acc = __ldg(b_dec + d);
#pragma unroll
    for (int j = 0; j < SAEK; j++)
        acc = fmaf(s_sel_v[j], __ldg(Wdec + (size_t)s_sel_i[j] * Kdim + d), acc);
    out[(size_t)row * Kdim + d] = acc;
}

// ---------------------------------------------------------------------------
extern "C" void kernel_launch(void* const* d_in, const int* in_sizes, int n_in,
                              void* d_out, int out_size)
{
    const float* x     = (const float*)d_in[0];
    const float* W_enc = (const float*)d_in[1];
    const float* b_enc = (const float*)d_in[2];
    const float* W_dec = (const float*)d_in[3];
    const float* b_dec = (const float*)d_in[4];
    float* out = (float*)d_out;

    static void* ccnt_ptr = nullptr;
    if (!ccnt_ptr) cudaGetSymbolAddress(&ccnt_ptr, g_ccnt);
    static bool attr = false;
    if (!attr) {
        cudaFuncSetAttribute(screen_gemm_s8, cudaFuncAttributeMaxDynamicSharedMemorySize,
                             3 * STAGE8);
        attr = true;
    }

    cudaMemsetAsync(ccnt_ptr, 0, Mdim * sizeof(int));
    stats_kernel<<<(Mdim + Ndim) / 8, 256>>>(x, W_enc, b_dec);
    prep_pack_s8<<<1024, 256>>>(x, W_enc, b_dec);

    dim3 g1(Ndim / 128, Mdim / 128);
    screen_gemm_s8<<<g1, 256, 3 * STAGE8>>>(b_enc);

    rescore_decode<<<Mdim, 256>>>(x, W_enc, b_enc, W_dec, b_dec, out);
}

// round 7
// speedup vs baseline: 3.7524x; 1.0750x over previous
#include <cuda_runtime.h>
#include <cstdint>

#define Mdim 8192
#define Ndim 8192
#define Kdim 256
#define SAEK 32
#define CCAP 512
#define TCOEF 0.1375f    // 2.2 sigma / 16
#define ECOEF 0.0100f    // int8 screening-error bound (abs / ||x||)

// ---------------- device scratch ----------------
__device__ uint32_t g_x8[(size_t)Mdim * Kdim / 4];   // int8 packed (x - b_dec)
__device__ uint32_t g_w8[(size_t)Ndim * Kdim / 4];   // int8 packed W_enc
__device__ float    g_rnorm[Mdim];
__device__ float    g_sx[Mdim],  g_isx[Mdim];
__device__ float    g_sw[Ndim],  g_isw[Ndim];
__device__ int      g_ccnt[Mdim];
__device__ int      g_cand_col[(size_t)Mdim * CCAP];
__device__ float    g_fbrow[(size_t)Mdim * Ndim];    // dense-fallback scratch (cold)

// ---------------- portable PTX helpers ----------------
__device__ __forceinline__ uint32_t smem_u32(const void* p) {
    uint32_t a;
    asm("{ .reg .u64 t; cvta.to.shared.u64 t, %1; cvt.u32.u64 %0, t; }" : "=r"(a) : "l"(p));
    return a;
}
__device__ __forceinline__ void cp_async16(uint32_t s, const void* g) {
    asm volatile("cp.async.cg.shared.global [%0], [%1], 16;" :: "r"(s), "l"(g));
}
#define CP_COMMIT() asm volatile("cp.async.commit_group;" ::: "memory")

#define LDSM_X4(r0,r1,r2,r3,addr) \
    asm volatile("ldmatrix.sync.aligned.m8n8.x4.shared.b16 {%0,%1,%2,%3}, [%4];" \
        : "=r"(r0),"=r"(r1),"=r"(r2),"=r"(r3) : "r"(addr))
#define LDSM_X2(r0,r1,addr) \
    asm volatile("ldmatrix.sync.aligned.m8n8.x2.shared.b16 {%0,%1}, [%2];" \
        : "=r"(r0),"=r"(r1) : "r"(addr))
#define MMA_S8(d,a,b) \
    asm volatile("mma.sync.aligned.m16n8k32.row.col.s32.s8.s8.s32 " \
        "{%0,%1,%2,%3},{%4,%5,%6,%7},{%8,%9},{%0,%1,%2,%3};" \
        : "+r"((d)[0]),"+r"((d)[1]),"+r"((d)[2]),"+r"((d)[3]) \
        : "r"((a)[0]),"r"((a)[1]),"r"((a)[2]),"r"((a)[3]),"r"((b)[0]),"r"((b)[1]))

// ---------------------------------------------------------------------------
// Kernel: per-row stats + candidate-counter zeroing. One warp per row.
// ---------------------------------------------------------------------------
__global__ __launch_bounds__(256)
void stats_kernel(const float* __restrict__ x, const float* __restrict__ Wenc,
                  const float* __restrict__ b_dec)
{
    const int wid = threadIdx.x >> 5, lane = threadIdx.x & 31;
    const int row = blockIdx.x * 8 + wid;
    if (row < Mdim) {
        const float* xr = x + (size_t)row * Kdim + lane * 8;
        float s = 0.f, mx = 0.f;
#pragma unroll
        for (int j = 0; j < 8; j++) {
            float e = xr[j] - __ldg(b_dec + lane * 8 + j);
            s = fmaf(e, e, s);
            mx = fmaxf(mx, fabsf(e));
        }
#pragma unroll
        for (int o = 16; o; o >>= 1) {
            s  += __shfl_down_sync(0xFFFFFFFFu, s, o);
            mx = fmaxf(mx, __shfl_down_sync(0xFFFFFFFFu, mx, o));
        }
        if (lane == 0) {
            g_rnorm[row] = sqrtf(s);
            g_sx[row]  = mx * (1.f / 127.f);
            g_isx[row] = (mx > 0.f) ? (127.f / mx) : 0.f;
            g_ccnt[row] = 0;
        }
    } else {
        const int r = row - Mdim;
        const float* wr = Wenc + (size_t)r * Kdim + lane * 8;
        float mx = 0.f;
#pragma unroll
        for (int j = 0; j < 8; j++) mx = fmaxf(mx, fabsf(wr[j]));
#pragma unroll
        for (int o = 16; o; o >>= 1) mx = fmaxf(mx, __shfl_down_sync(0xFFFFFFFFu, mx, o));
        if (lane == 0) {
            g_sw[r]  = mx * (1.f / 127.f);
            g_isw[r] = (mx > 0.f) ? (127.f / mx) : 0.f;
        }
    }
}

// ---------------------------------------------------------------------------
// Kernel: quantize (x - b_dec) and W_enc to int8 (16 elements / thread)
// ---------------------------------------------------------------------------
__device__ __forceinline__ uint32_t q4(const float* v, float inv) {
    int q0 = max(-127, min(127, __float2int_rn(v[0] * inv)));
    int q1 = max(-127, min(127, __float2int_rn(v[1] * inv)));
    int q2 = max(-127, min(127, __float2int_rn(v[2] * inv)));
    int q3 = max(-127, min(127, __float2int_rn(v[3] * inv)));
    return (uint32_t)(q0 & 255) | ((uint32_t)(q1 & 255) << 8) |
           ((uint32_t)(q2 & 255) << 16) | ((uint32_t)(q3 & 255) << 24);
}

__global__ __launch_bounds__(256)
void prep_pack_s8(const float* __restrict__ x, const float* __restrict__ Wenc,
                  const float* __restrict__ b_dec)
{
    const size_t XT = (size_t)Mdim * Kdim / 16;
    size_t i = (size_t)blockIdx.x * 256 + threadIdx.x;
    float v[16];
    float inv;
    uint32_t* dst;
    if (i < XT) {
        const size_t base = i * 16;
        const int row = (int)(base >> 8);
        const int k = (int)(base & (Kdim - 1));
        inv = __ldg(g_isx + row);
#pragma unroll
        for (int j = 0; j < 16; j += 4) {
            float4 a = *(const float4*)(x + base + j);
            v[j]   = a.x - __ldg(b_dec + k + j);
            v[j+1] = a.y - __ldg(b_dec + k + j + 1);
            v[j+2] = a.z - __ldg(b_dec + k + j + 2);
            v[j+3] = a.w - __ldg(b_dec + k + j + 3);
        }
        dst = g_x8 + i * 4;
    } else {
        const size_t base = (i - XT) * 16;
        const int row = (int)(base >> 8);
        inv = __ldg(g_isw + row);
#pragma unroll
        for (int j = 0; j < 16; j += 4) {
            float4 a = *(const float4*)(Wenc + base + j);
            v[j] = a.x; v[j+1] = a.y; v[j+2] = a.z; v[j+3] = a.w;
        }
        dst = g_w8 + (i - XT) * 4;
    }
    uint4 o;
    o.x = q4(v + 0,  inv);
    o.y = q4(v + 4,  inv);
    o.z = q4(v + 8,  inv);
    o.w = q4(v + 12, inv);
    *(uint4*)dst = o;
}

// ---------------------------------------------------------------------------
// Kernel: int8 screening GEMM, 128x128 tile, 3-stage cp.async,
// single barrier per K-chunk (prefetch moved inside the barrier shadow).
// ---------------------------------------------------------------------------
#define SROW 48u
#define TILE8 (128u * SROW)      // 6144 B
#define STAGE8 (2u * TILE8)      // 12288 B

__global__ __launch_bounds__(256, 2)
void screen_gemm_s8(const float* __restrict__ b_enc)
{
    extern __shared__ char smc[];
    const uint32_t smb = smem_u32(smc);
    const int tid = threadIdx.x, lane = tid & 31, wid = tid >> 5;
    const int wm = wid & 1, wn = wid >> 1;
    const int m0 = blockIdx.y * 128, n0 = blockIdx.x * 128;

    int acc[4][4][4];
#pragma unroll
    for (int a = 0; a < 4; a++)
#pragma unroll
        for (int b = 0; b < 4; b++)
#pragma unroll
            for (int c = 0; c < 4; c++) acc[a][b][c] = 0;

    const int prow = tid >> 1;
    const int half = tid & 1;

    auto prefetch = [&](int c) {
        const uint32_t st = smb + (uint32_t)(c % 3) * STAGE8;
        const uint32_t da = st + (uint32_t)prow * SROW + (uint32_t)half * 16u;
        const char* ga = (const char*)g_x8 + (size_t)(m0 + prow) * Kdim + c * 32 + half * 16;
        const char* gb = (const char*)g_w8 + (size_t)(n0 + prow) * Kdim + c * 32 + half * 16;
        cp_async16(da,         ga);
        cp_async16(da + TILE8, gb);
        CP_COMMIT();
    };

    prefetch(0); prefetch(1);

    for (int c = 0; c < 8; c++) {
        if (c < 7) asm volatile("cp.async.wait_group 1;" ::: "memory");
        else       asm volatile("cp.async.wait_group 0;" ::: "memory");
        __syncthreads();
        // stage (c+2)%3 == (c-1)%3 is dead past the barrier above
        if (c + 2 < 8) prefetch(c + 2);

        const uint32_t sA = smb + (uint32_t)(c % 3) * STAGE8;
        const uint32_t sB = sA + TILE8;

        uint32_t af[4][4], bf[4][2];
#pragma unroll
        for (int mt = 0; mt < 4; mt++) {
            const uint32_t ad = sA + (uint32_t)(wm * 64 + mt * 16 + (lane & 15)) * SROW
                              + (uint32_t)((lane >> 4) * 16);
            LDSM_X4(af[mt][0], af[mt][1], af[mt][2], af[mt][3], ad);
        }
#pragma unroll
        for (int nt = 0; nt < 4; nt++) {
            const uint32_t bd = sB + (uint32_t)(wn * 32 + nt * 8 + (lane & 7)) * SROW
                              + (uint32_t)(((lane >> 3) & 1) * 16);
            LDSM_X2(bf[nt][0], bf[nt][1], bd);
        }
#pragma unroll
        for (int mt = 0; mt < 4; mt++)
#pragma unroll
            for (int nt = 0; nt < 4; nt++)
                MMA_S8(acc[mt][nt], af[mt], bf[nt]);
    }

    // epilogue: dequant + threshold append
#pragma unroll
    for (int mt = 0; mt < 4; mt++) {
        const int r0 = m0 + wm * 64 + mt * 16 + (lane >> 2);
        const int r1 = r0 + 8;
        const float sx0 = __ldg(g_sx + r0), sx1 = __ldg(g_sx + r1);
        const float T0 = TCOEF * __ldg(g_rnorm + r0);
        const float T1 = TCOEF * __ldg(g_rnorm + r1);
#pragma unroll
        for (int nt = 0; nt < 4; nt++) {
            const int c0 = n0 + wn * 32 + nt * 8 + 2 * (lane & 3);
            const float sw0 = __ldg(g_sw + c0), sw1 = __ldg(g_sw + c0 + 1);
            const float be0 = __ldg(b_enc + c0), be1 = __ldg(b_enc + c0 + 1);
            float v0 = (float)acc[mt][nt][0] * (sx0 * sw0) + be0;
            float v1 = (float)acc[mt][nt][1] * (sx0 * sw1) + be1;
            float v2 = (float)acc[mt][nt][2] * (sx1 * sw0) + be0;
            float v3 = (float)acc[mt][nt][3] * (sx1 * sw1) + be1;
            if (v0 >= T0) { int p = atomicAdd(&g_ccnt[r0], 1); if (p < CCAP) g_cand_col[(size_t)r0 * CCAP + p] = c0; }
            if (v1 >= T0) { int p = atomicAdd(&g_ccnt[r0], 1); if (p < CCAP) g_cand_col[(size_t)r0 * CCAP + p] = c0 + 1; }
            if (v2 >= T1) { int p = atomicAdd(&g_ccnt[r1], 1); if (p < CCAP) g_cand_col[(size_t)r1 * CCAP + p] = c0; }
            if (v3 >= T1) { int p = atomicAdd(&g_ccnt[r1], 1); if (p < CCAP) g_cand_col[(size_t)r1 * CCAP + p] = c0 + 1; }
        }
    }
}

// ---------------------------------------------------------------------------
// Kernel: exact fp32 rescore (cp.async double-buffered candidate gather)
//         + one-pass rank top-32 + fused decode.
// ---------------------------------------------------------------------------
__global__ __launch_bounds__(256)
void rescore_decode(const float* __restrict__ x, const float* __restrict__ Wenc,
                    const float* __restrict__ b_enc, const float* __restrict__ Wdec,
                    const float* __restrict__ b_dec, float* __restrict__ out)
{
    __shared__ float s_x[Kdim];
    __shared__ __align__(16) float s_w[8][2][Kdim];   // 16 KB candidate buffers
    __shared__ int   s_col[CCAP];
    __shared__ float s_val[CCAP];
    __shared__ float s_sel_v[SAEK];
    __shared__ int   s_sel_i[SAEK];
    __shared__ float s_rv[8];
    __shared__ int   s_ri[8];
    __shared__ int   s_fb;

    const int row = blockIdx.x;
    const int tid = threadIdx.x;
    const int wid = tid >> 5, lane = tid & 31;

    s_x[tid] = x[(size_t)row * Kdim + tid] - __ldg(b_dec + tid);
    if (tid == 0) s_fb = 0;
    __syncthreads();

    float xr[8];
#pragma unroll
    for (int j = 0; j < 8; j++) xr[j] = s_x[lane * 8 + j];

    const int n = g_ccnt[row];
    const float rn = g_rnorm[row];
    bool fb = (n < SAEK) || (n > CCAP);

    if (!fb) {
        for (int i = tid; i < n; i += 256) s_col[i] = g_cand_col[(size_t)row * CCAP + i];
        __syncthreads();

        // per-lane buffer addresses: lane writes & reads ITS OWN 32 bytes,
        // so no cross-thread smem visibility is needed.
        const uint32_t wb0 = smem_u32(&s_w[wid][0][0]) + (uint32_t)lane * 32u;
        const uint32_t wb1 = smem_u32(&s_w[wid][1][0]) + (uint32_t)lane * 32u;

        if (wid < n) {   // n >= 32 > 8, always true, kept for safety
            const char* src = (const char*)(Wenc + (size_t)s_col[wid] * Kdim) + lane * 32;
            cp_async16(wb0,      src);
            cp_async16(wb0 + 16, src + 16);
        }
        CP_COMMIT();

        int buf = 0;
        for (int c = wid; c < n; c += 8, buf ^= 1) {
            const int cn = c + 8;
            if (cn < n) {
                const uint32_t d = buf ? wb0 : wb1;
                const char* src = (const char*)(Wenc + (size_t)s_col[cn] * Kdim) + lane * 32;
                cp_async16(d,      src);
                cp_async16(d + 16, src + 16);
            }
            CP_COMMIT();
            asm volatile("cp.async.wait_group 1;" ::: "memory");

            const float* wr = &s_w[wid][buf][lane * 8];
            float4 w0 = *(const float4*)wr;
            float4 w1 = *(const float4*)(wr + 4);
            float s = xr[0] * w0.x;
            s = fmaf(xr[1], w0.y, s); s = fmaf(xr[2], w0.z, s); s = fmaf(xr[3], w0.w, s);
            s = fmaf(xr[4], w1.x, s); s = fmaf(xr[5], w1.y, s); s = fmaf(xr[6], w1.z, s);
            s = fmaf(xr[7], w1.w, s);
#pragma unroll
            for (int o = 16; o; o >>= 1) s += __shfl_xor_sync(0xFFFFFFFFu, s, o);
            if (lane == 0) s_val[c] = s + __ldg(b_enc + s_col[c]);
        }
        asm volatile("cp.async.wait_group 0;" ::: "memory");
        __syncthreads();

        // one-pass rank selection (keys unique: (val desc, col asc))
        for (int i = tid; i < n; i += 256) {
            const float vi = s_val[i];
            const int   ci = s_col[i];
            int r = 0;
            for (int j = 0; j < n; j++) {
                const float vj = s_val[j];
                r += (vj > vi) || (vj == vi && s_col[j] < ci);
            }
            if (r < SAEK) { s_sel_v[r] = vi; s_sel_i[r] = ci; }
        }
        __syncthreads();

        // validity gate
        if (tid == 0 && s_sel_v[SAEK - 1] < (TCOEF + ECOEF) * rn + 1e-6f) s_fb = 1;
        __syncthreads();
        fb = (s_fb != 0);
    }

    if (fb) {
        // dense exact fallback via global scratch (statistically never taken)
        float* frow = g_fbrow + (size_t)row * Ndim;
        for (int col = tid; col < Ndim; col += 256) {
            const float* wr = Wenc + (size_t)col * Kdim;
            float a = 0.f;
            for (int d = 0; d < Kdim; d += 4) {
                float4 w = *(const float4*)(wr + d);
                a = fmaf(s_x[d], w.x, a);     a = fmaf(s_x[d + 1], w.y, a);
                a = fmaf(s_x[d + 2], w.z, a); a = fmaf(s_x[d + 3], w.w, a);
            }
            frow[col] = fmaxf(a + __ldg(b_enc + col), 0.f);
        }
        __syncthreads();
        for (int it = 0; it < SAEK; it++) {
            float bv = -1e30f; int bi = 0x7FFFFFFF;
            for (int i = tid; i < Ndim; i += 256) {
                float v = frow[i];
                if (v > bv || (v == bv && i < bi)) { bv = v; bi = i; }
            }
#pragma unroll
            for (int o = 16; o; o >>= 1) {
                float ov = __shfl_down_sync(0xFFFFFFFFu, bv, o);
                int   oi = __shfl_down_sync(0xFFFFFFFFu, bi, o);
                if (ov > bv || (ov == bv && oi < bi)) { bv = ov; bi = oi; }
            }
            if (lane == 0) { s_rv[wid] = bv; s_ri[wid] = bi; }
            __syncthreads();
            if (tid == 0) {
                float wv = s_rv[0]; int wi = s_ri[0];
#pragma unroll
                for (int j = 1; j < 8; j++)
                    if (s_rv[j] > wv || (s_rv[j] == wv && s_ri[j] < wi)) { wv = s_rv[j]; wi = s_ri[j]; }
                s_sel_v[it] = wv; s_sel_i[it] = wi;
                frow[wi] = -1e30f;
            }
            __syncthreads();
        }
    }

    // fused decode
    const int d = tid;
    float acc = __ldg(b_dec + d);
#pragma unroll
    for (int j = 0; j < SAEK; j++)
        acc = fmaf(s_sel_v[j], __ldg(Wdec + (size_t)s_sel_i[j] * Kdim + d), acc);
    out[(size_t)row * Kdim + d] = acc;
}

// ---------------------------------------------------------------------------
extern "C" void kernel_launch(void* const* d_in, const int* in_sizes, int n_in,
                              void* d_out, int out_size)
{
    const float* x     = (const float*)d_in[0];
    const float* W_enc = (const float*)d_in[1];
    const float* b_enc = (const float*)d_in[2];
    const float* W_dec = (const float*)d_in[3];
    const float* b_dec = (const float*)d_in[4];
    float* out = (float*)d_out;

    stats_kernel<<<(Mdim + Ndim) / 8, 256>>>(x, W_enc, b_dec);
    prep_pack_s8<<<1024, 256>>>(x, W_enc, b_dec);

    dim3 g1(Ndim / 128, Mdim / 128);
    screen_gemm_s8<<<g1, 256, 3 * STAGE8>>>(b_enc);

    rescore_decode<<<Mdim, 256>>>(x, W_enc, b_enc, W_dec, b_dec, out);
}